// round 1
// baseline (speedup 1.0000x reference)
#include <cuda_runtime.h>
#include <math.h>

#define DIM   1024
#define NC    8
#define NPER  4096
#define QDIM  128
#define TOPK  128

// Scratch (no allocations allowed -> __device__ globals)
__device__ float g_w[NC][DIM];        // q_w^T @ qk per cluster
__device__ float g_b0[NC];            // q_b . qk
__device__ float g_s[NC][NPER];       // scaled logits
__device__ float g_coef[NC][NPER];    // softmax weights A
__device__ int   g_topidx[NC][TOPK];  // sorted top-k indices
__device__ float g_gvec[NC][DIM];     // A^T @ feats

// ---------------------------------------------------------------------------
// Kernel A: per-cluster qk = key@q_w^T + q_b ; w = q_w^T @ qk ; b0 = q_b.qk
// grid = NC, block = 128
// ---------------------------------------------------------------------------
__global__ void prep_kernel(const float* __restrict__ key_feats,
                            const float* __restrict__ q_w,
                            const float* __restrict__ q_b) {
    __shared__ float s_qk[QDIM];
    __shared__ float red[QDIM];
    int c = blockIdx.x;
    int t = threadIdx.x;  // 0..127

    // qk[t] = key[c] . q_w[t,:] + q_b[t]
    const float4* kr = (const float4*)(key_feats + (size_t)c * DIM);
    const float4* qr = (const float4*)(q_w + (size_t)t * DIM);
    float acc = 0.f;
    for (int i = 0; i < DIM / 4; i++) {
        float4 a = qr[i], b = kr[i];
        acc += a.x * b.x + a.y * b.y + a.z * b.z + a.w * b.w;
    }
    s_qk[t] = acc + q_b[t];
    __syncthreads();

    // w[d] = sum_q qk[q] * q_w[q, d]
    for (int i = 0; i < DIM / QDIM; i++) {
        int d = t + i * QDIM;
        float wacc = 0.f;
        #pragma unroll 8
        for (int q = 0; q < QDIM; q++)
            wacc += s_qk[q] * q_w[(size_t)q * DIM + d];
        g_w[c][d] = wacc;
    }

    // b0 = qk . q_b
    red[t] = s_qk[t] * q_b[t];
    __syncthreads();
    for (int o = 64; o > 0; o >>= 1) {
        if (t < o) red[t] += red[t + o];
        __syncthreads();
    }
    if (t == 0) g_b0[c] = red[0];
}

// ---------------------------------------------------------------------------
// Kernel B: s[c][n] = (feats[c][n] . w[c] + b0[c]) / sqrt(QDIM)
// grid = NC*NPER/8, block = 256 (8 warps, one row each)
// ---------------------------------------------------------------------------
__global__ void score_kernel(const float* __restrict__ feats) {
    __shared__ float sw[DIM];
    int bid = blockIdx.x;
    int c = bid / (NPER / 8);
    int r0 = (bid % (NPER / 8)) * 8;
    int t = threadIdx.x;

    ((float4*)sw)[t] = ((const float4*)(g_w[c]))[t];  // 256 * float4 = 1024
    __syncthreads();

    int warp = t >> 5, lane = t & 31;
    int row = r0 + warp;
    const float4* fr = (const float4*)(feats + ((size_t)c * NPER + row) * DIM);
    const float4* wr = (const float4*)sw;
    float acc = 0.f;
    #pragma unroll
    for (int i = 0; i < 8; i++) {
        int idx = lane + i * 32;
        float4 a = fr[idx], b = wr[idx];
        acc += a.x * b.x + a.y * b.y + a.z * b.z + a.w * b.w;
    }
    #pragma unroll
    for (int o = 16; o > 0; o >>= 1)
        acc += __shfl_xor_sync(0xffffffffu, acc, o);
    if (lane == 0)
        g_s[c][row] = (acc + g_b0[c]) * 0.08838834764831845f;  // 1/sqrt(128)
}

// ---------------------------------------------------------------------------
// Kernel C: per cluster — full bitonic sort of 4096 (desc value, asc index),
// softmax coefs, top-128 indices, and zero g_gvec for pass 2.
// grid = NC, block = 1024
// ---------------------------------------------------------------------------
__global__ __launch_bounds__(1024) void topk_softmax_kernel() {
    __shared__ unsigned long long keys[NPER];  // 32 KB
    __shared__ float red[1024];
    __shared__ float s_max;
    int c = blockIdx.x;
    int t = threadIdx.x;

    float v[4];
    #pragma unroll
    for (int i = 0; i < 4; i++) {
        int n = t + i * 1024;
        float val = g_s[c][n];
        v[i] = val;
        unsigned u = __float_as_uint(val);
        u = (u & 0x80000000u) ? ~u : (u | 0x80000000u);  // ascending map
        unsigned d = ~u;                                 // descending map
        keys[n] = ((unsigned long long)d << 32) | (unsigned)n;
    }
    __syncthreads();

    // bitonic sort ascending on key => descending value, ascending idx on ties
    for (unsigned k = 2; k <= NPER; k <<= 1) {
        for (unsigned j = k >> 1; j > 0; j >>= 1) {
            #pragma unroll
            for (int ii = 0; ii < 4; ii++) {
                unsigned i = (unsigned)t + ii * 1024u;
                unsigned ixj = i ^ j;
                if (ixj > i) {
                    unsigned long long a = keys[i], b = keys[ixj];
                    bool up = ((i & k) == 0);
                    if ((a > b) == up) { keys[i] = b; keys[ixj] = a; }
                }
            }
            __syncthreads();
        }
    }

    if (t < TOPK)
        g_topidx[c][t] = (int)(unsigned)(keys[t] & 0xffffffffu);
    if (t == 0) {
        unsigned d = (unsigned)(keys[0] >> 32);
        unsigned u = ~d;
        unsigned vb = (u & 0x80000000u) ? (u ^ 0x80000000u) : ~u;
        s_max = __uint_as_float(vb);
    }
    __syncthreads();

    float m = s_max;
    float e[4], psum = 0.f;
    #pragma unroll
    for (int i = 0; i < 4; i++) { e[i] = expf(v[i] - m); psum += e[i]; }
    red[t] = psum;
    __syncthreads();
    for (int o = 512; o > 0; o >>= 1) {
        if (t < o) red[t] += red[t + o];
        __syncthreads();
    }
    float invZ = 1.f / red[0];
    #pragma unroll
    for (int i = 0; i < 4; i++)
        g_coef[c][t + i * 1024] = e[i] * invZ;

    g_gvec[c][t] = 0.f;  // zero accumulator for pass 2 (t covers all 1024)
}

// ---------------------------------------------------------------------------
// Kernel D: gather selected rows: out[c*128+k] = feats[c][topidx[c][k]]
// grid = 1024, block = 256
// ---------------------------------------------------------------------------
__global__ void gather_kernel(const float* __restrict__ feats,
                              float* __restrict__ out) {
    int row = blockIdx.x;
    int c = row >> 7, k = row & 127;
    int src = g_topidx[c][k];
    const float4* s = (const float4*)(feats + ((size_t)c * NPER + src) * DIM);
    float4* dst = (float4*)(out + (size_t)row * DIM);
    dst[threadIdx.x] = s[threadIdx.x];
}

// ---------------------------------------------------------------------------
// Kernel E: g[c] += sum_n A[c][n] * feats[c][n]  (second pass over feats)
// grid = NC*32 (chunks of 128 rows), block = 256 (float4 per thread = 1024 cols)
// ---------------------------------------------------------------------------
__global__ void wsum_kernel(const float* __restrict__ feats) {
    __shared__ float sc[128];
    int bid = blockIdx.x;
    int c = bid >> 5;
    int chunk = bid & 31;
    int t = threadIdx.x;

    if (t < 128) sc[t] = g_coef[c][chunk * 128 + t];
    __syncthreads();

    const float* base = feats + ((size_t)c * NPER + (size_t)chunk * 128) * DIM;
    float4 acc = make_float4(0.f, 0.f, 0.f, 0.f);
    for (int r = 0; r < 128; r++) {
        float4 f = ((const float4*)(base + (size_t)r * DIM))[t];
        float a = sc[r];
        acc.x += a * f.x; acc.y += a * f.y; acc.z += a * f.z; acc.w += a * f.w;
    }
    float* gp = g_gvec[c] + t * 4;
    atomicAdd(gp + 0, acc.x);
    atomicAdd(gp + 1, acc.y);
    atomicAdd(gp + 2, acc.z);
    atomicAdd(gp + 3, acc.w);
}

// ---------------------------------------------------------------------------
// Kernel F: fusion[c][o] = g[c] . v_w[o,:] + v_b[o]
// grid = NC*128 (8 outputs per block), block = 256 (8 warps)
// ---------------------------------------------------------------------------
__global__ void fusion_kernel(const float* __restrict__ v_w,
                              const float* __restrict__ v_b,
                              float* __restrict__ out) {
    __shared__ float sg[DIM];
    int bid = blockIdx.x;
    int c = bid >> 7;
    int o0 = (bid & 127) * 8;
    int t = threadIdx.x;

    ((float4*)sg)[t] = ((const float4*)(g_gvec[c]))[t];
    __syncthreads();

    int warp = t >> 5, lane = t & 31;
    int o = o0 + warp;
    const float4* vr = (const float4*)(v_w + (size_t)o * DIM);
    const float4* gr = (const float4*)sg;
    float acc = 0.f;
    #pragma unroll
    for (int i = 0; i < 8; i++) {
        int idx = lane + i * 32;
        float4 a = vr[idx], b = gr[idx];
        acc += a.x * b.x + a.y * b.y + a.z * b.z + a.w * b.w;
    }
    #pragma unroll
    for (int ofs = 16; ofs > 0; ofs >>= 1)
        acc += __shfl_xor_sync(0xffffffffu, acc, ofs);
    if (lane == 0)
        out[(size_t)1024 * 1024 + (size_t)c * DIM + o] = acc + v_b[o];
}

// ---------------------------------------------------------------------------
extern "C" void kernel_launch(void* const* d_in, const int* in_sizes, int n_in,
                              void* d_out, int out_size) {
    const float* feats     = (const float*)d_in[0];  // [8,4096,1024]
    const float* key_feats = (const float*)d_in[1];  // [8,1,1024]
    const float* q_w       = (const float*)d_in[2];  // [128,1024]
    const float* q_b       = (const float*)d_in[3];  // [128]
    const float* v_w       = (const float*)d_in[4];  // [1024,1024]
    const float* v_b       = (const float*)d_in[5];  // [1024]
    float* out = (float*)d_out;  // selected [1024,1024] then fus [8,1024]

    prep_kernel<<<NC, QDIM>>>(key_feats, q_w, q_b);
    score_kernel<<<NC * NPER / 8, 256>>>(feats);
    topk_softmax_kernel<<<NC, 1024>>>();
    gather_kernel<<<NC * TOPK, 256>>>(feats, out);
    wsum_kernel<<<NC * 32, 256>>>(feats);
    fusion_kernel<<<NC * 128, 256>>>(v_w, v_b, out);
}

// round 2
// speedup vs baseline: 1.0294x; 1.0294x over previous
#include <cuda_runtime.h>
#include <math.h>

#define DIM   1024
#define NC    8
#define NPER  4096
#define QDIM  128
#define TOPK  128

// Scratch (no allocations allowed -> __device__ globals)
__device__ float g_w[NC][DIM];        // q_w^T @ qk per cluster
__device__ float g_b0[NC];            // q_b . qk
__device__ float g_s[NC][NPER];       // scaled logits
__device__ int   g_topidx[NC][TOPK];  // sorted top-k indices
__device__ float g_gvec[NC][DIM];     // unnormalized sum_n e^{s_n} feats[n]
__device__ float g_Z[NC];             // sum_n e^{s_n}

// ---------------------------------------------------------------------------
// Kernel A: per-cluster qk = key@q_w^T + q_b ; w = q_w^T @ qk ; b0 = q_b.qk
// Also zeroes g_gvec / g_Z accumulators for this launch.
// grid = NC, block = 128
// ---------------------------------------------------------------------------
__global__ void prep_kernel(const float* __restrict__ key_feats,
                            const float* __restrict__ q_w,
                            const float* __restrict__ q_b) {
    __shared__ float s_qk[QDIM];
    __shared__ float red[QDIM];
    int c = blockIdx.x;
    int t = threadIdx.x;  // 0..127

    // zero accumulators (deterministic every launch)
    #pragma unroll
    for (int i = 0; i < DIM / QDIM; i++) g_gvec[c][t + i * QDIM] = 0.f;
    if (t == 0) g_Z[c] = 0.f;

    // qk[t] = key[c] . q_w[t,:] + q_b[t]
    const float4* kr = (const float4*)(key_feats + (size_t)c * DIM);
    const float4* qr = (const float4*)(q_w + (size_t)t * DIM);
    float acc = 0.f;
    for (int i = 0; i < DIM / 4; i++) {
        float4 a = qr[i], b = kr[i];
        acc += a.x * b.x + a.y * b.y + a.z * b.z + a.w * b.w;
    }
    s_qk[t] = acc + q_b[t];
    __syncthreads();

    // w[d] = sum_q qk[q] * q_w[q, d]
    for (int i = 0; i < DIM / QDIM; i++) {
        int d = t + i * QDIM;
        float wacc = 0.f;
        #pragma unroll 8
        for (int q = 0; q < QDIM; q++)
            wacc += s_qk[q] * q_w[(size_t)q * DIM + d];
        g_w[c][d] = wacc;
    }

    // b0 = qk . q_b
    red[t] = s_qk[t] * q_b[t];
    __syncthreads();
    for (int o = 64; o > 0; o >>= 1) {
        if (t < o) red[t] += red[t + o];
        __syncthreads();
    }
    if (t == 0) g_b0[c] = red[0];
}

// ---------------------------------------------------------------------------
// Kernel B (fused single pass over feats):
//   s_n = (f_n . w + b0) / sqrt(QDIM)      -> g_s
//   e_n = exp(s_n)   (|s| ~ N(0,1), safe without max subtraction)
//   gvec += sum_n e_n * f_n  ;  Z += sum_n e_n   (atomics across blocks)
// grid = NC*64 (64 rows per block), block = 256
// ---------------------------------------------------------------------------
__global__ __launch_bounds__(256) void fused_pass_kernel(const float* __restrict__ feats) {
    __shared__ float srow[8 * DIM];   // 8 staged rows (32 KB)
    __shared__ float sw[DIM];         // w vector (4 KB)
    __shared__ float se[8];           // exp weights for staged rows

    int bid = blockIdx.x;
    int c = bid >> 6;
    int row_base = (bid & 63) * 64;
    int t = threadIdx.x;
    int warp = t >> 5, lane = t & 31;

    ((float4*)sw)[t] = ((const float4*)(g_w[c]))[t];  // 256 float4 = 1024 f
    float b0 = g_b0[c];
    __syncthreads();

    const float4* fbase =
        (const float4*)(feats + ((size_t)c * NPER + row_base) * DIM);

    float4 acc = make_float4(0.f, 0.f, 0.f, 0.f);
    float zloc = 0.f;

    for (int iter = 0; iter < 8; iter++) {
        // stage 8 rows (2048 float4), coalesced: thread t -> row i, col4 t
        const float4* src = fbase + (size_t)iter * 8 * (DIM / 4);
        #pragma unroll
        for (int i = 0; i < 8; i++)
            ((float4*)srow)[i * 256 + t] = src[i * 256 + t];
        __syncthreads();

        // warp w computes dot of staged row w
        {
            const float4* fr = (const float4*)(srow + warp * DIM);
            const float4* wr = (const float4*)sw;
            float d = 0.f;
            #pragma unroll
            for (int k = 0; k < 8; k++) {
                int idx = lane + k * 32;
                float4 a = fr[idx], b = wr[idx];
                d += a.x * b.x + a.y * b.y + a.z * b.z + a.w * b.w;
            }
            #pragma unroll
            for (int o = 16; o > 0; o >>= 1)
                d += __shfl_xor_sync(0xffffffffu, d, o);
            if (lane == 0) {
                float s = (d + b0) * 0.08838834764831845f;  // 1/sqrt(128)
                g_s[c][row_base + iter * 8 + warp] = s;
                se[warp] = expf(s);
            }
        }
        __syncthreads();

        // accumulate exp-weighted rows: thread t owns col4 t
        #pragma unroll
        for (int r = 0; r < 8; r++) {
            float a = se[r];
            float4 f = ((const float4*)(srow + r * DIM))[t];
            acc.x += a * f.x; acc.y += a * f.y;
            acc.z += a * f.z; acc.w += a * f.w;
        }
        if (t == 0) {
            #pragma unroll
            for (int r = 0; r < 8; r++) zloc += se[r];
        }
        __syncthreads();  // protect srow/se before next stage
    }

    float* gp = g_gvec[c] + t * 4;
    atomicAdd(gp + 0, acc.x);
    atomicAdd(gp + 1, acc.y);
    atomicAdd(gp + 2, acc.z);
    atomicAdd(gp + 3, acc.w);
    if (t == 0) atomicAdd(&g_Z[c], zloc);
}

// ---------------------------------------------------------------------------
// Kernel C: per cluster — full bitonic sort of 4096 scores
// (desc value, asc index on ties), emit top-128 indices.
// grid = NC, block = 1024
// ---------------------------------------------------------------------------
__global__ __launch_bounds__(1024) void topk_kernel() {
    __shared__ unsigned long long keys[NPER];  // 32 KB
    int c = blockIdx.x;
    int t = threadIdx.x;

    #pragma unroll
    for (int i = 0; i < 4; i++) {
        int n = t + i * 1024;
        unsigned u = __float_as_uint(g_s[c][n]);
        u = (u & 0x80000000u) ? ~u : (u | 0x80000000u);  // ascending map
        unsigned d = ~u;                                 // descending map
        keys[n] = ((unsigned long long)d << 32) | (unsigned)n;
    }
    __syncthreads();

    for (unsigned k = 2; k <= NPER; k <<= 1) {
        for (unsigned j = k >> 1; j > 0; j >>= 1) {
            #pragma unroll
            for (int ii = 0; ii < 4; ii++) {
                unsigned i = (unsigned)t + ii * 1024u;
                unsigned ixj = i ^ j;
                if (ixj > i) {
                    unsigned long long a = keys[i], b = keys[ixj];
                    bool up = ((i & k) == 0);
                    if ((a > b) == up) { keys[i] = b; keys[ixj] = a; }
                }
            }
            __syncthreads();
        }
    }

    if (t < TOPK)
        g_topidx[c][t] = (int)(unsigned)(keys[t] & 0xffffffffu);
}

// ---------------------------------------------------------------------------
// Kernel D: gather selected rows: out[c*128+k] = feats[c][topidx[c][k]]
// grid = 512 (2 rows/block), block = 256
// ---------------------------------------------------------------------------
__global__ void gather_kernel(const float* __restrict__ feats,
                              float* __restrict__ out) {
    int t = threadIdx.x;
    #pragma unroll
    for (int rr = 0; rr < 2; rr++) {
        int row = blockIdx.x * 2 + rr;
        int c = row >> 7, k = row & 127;
        int src = g_topidx[c][k];
        const float4* s =
            (const float4*)(feats + ((size_t)c * NPER + src) * DIM);
        float4* dst = (float4*)(out + (size_t)row * DIM);
        dst[t] = s[t];
    }
}

// ---------------------------------------------------------------------------
// Kernel E: fusion[c][o] = (gvec[c]/Z[c]) . v_w[o,:] + v_b[o]
// grid = NC*128 (8 outputs per block), block = 256 (8 warps)
// ---------------------------------------------------------------------------
__global__ void fusion_kernel(const float* __restrict__ v_w,
                              const float* __restrict__ v_b,
                              float* __restrict__ out) {
    __shared__ float sg[DIM];
    int bid = blockIdx.x;
    int c = bid >> 7;
    int o0 = (bid & 127) * 8;
    int t = threadIdx.x;

    float invZ = 1.f / g_Z[c];
    float4 gv = ((const float4*)(g_gvec[c]))[t];
    gv.x *= invZ; gv.y *= invZ; gv.z *= invZ; gv.w *= invZ;
    ((float4*)sg)[t] = gv;
    __syncthreads();

    int warp = t >> 5, lane = t & 31;
    int o = o0 + warp;
    const float4* vr = (const float4*)(v_w + (size_t)o * DIM);
    const float4* gr = (const float4*)sg;
    float acc = 0.f;
    #pragma unroll
    for (int i = 0; i < 8; i++) {
        int idx = lane + i * 32;
        float4 a = vr[idx], b = gr[idx];
        acc += a.x * b.x + a.y * b.y + a.z * b.z + a.w * b.w;
    }
    #pragma unroll
    for (int ofs = 16; ofs > 0; ofs >>= 1)
        acc += __shfl_xor_sync(0xffffffffu, acc, ofs);
    if (lane == 0)
        out[(size_t)1024 * 1024 + (size_t)c * DIM + o] = acc + v_b[o];
}

// ---------------------------------------------------------------------------
extern "C" void kernel_launch(void* const* d_in, const int* in_sizes, int n_in,
                              void* d_out, int out_size) {
    const float* feats     = (const float*)d_in[0];  // [8,4096,1024]
    const float* key_feats = (const float*)d_in[1];  // [8,1,1024]
    const float* q_w       = (const float*)d_in[2];  // [128,1024]
    const float* q_b       = (const float*)d_in[3];  // [128]
    const float* v_w       = (const float*)d_in[4];  // [1024,1024]
    const float* v_b       = (const float*)d_in[5];  // [1024]
    float* out = (float*)d_out;  // selected [1024,1024] then fus [8,1024]

    prep_kernel<<<NC, QDIM>>>(key_feats, q_w, q_b);
    fused_pass_kernel<<<NC * 64, 256>>>(feats);
    topk_kernel<<<NC, 1024>>>();
    gather_kernel<<<512, 256>>>(feats, out);
    fusion_kernel<<<NC * 128, 256>>>(v_w, v_b, out);
}

// round 3
// speedup vs baseline: 2.4177x; 2.3486x over previous
#include <cuda_runtime.h>
#include <math.h>

#define DIM   1024
#define NC    8
#define NPER  4096
#define QDIM  128
#define TOPK  128

// Scratch (no allocations allowed -> __device__ globals)
__device__ float g_w[NC][DIM];                   // q_w^T @ qk per cluster
__device__ float g_b0[NC];                       // q_b . qk
__device__ unsigned long long g_keys[NC][NPER];  // (desc-map(score)<<32)|idx
__device__ int   g_topidx[NC][TOPK];             // sorted top-k indices
__device__ float g_gvec[NC][DIM];                // sum_n e^{s_n} feats[n]
__device__ float g_Z[NC];                        // sum_n e^{s_n}

// ---------------------------------------------------------------------------
// Kernel A: per-cluster qk = key@q_w^T + q_b ; w = q_w^T @ qk ; b0 = q_b.qk
// Also zeroes g_gvec / g_Z. grid = NC, block = 1024.
// ---------------------------------------------------------------------------
__global__ __launch_bounds__(1024) void prep_kernel(const float* __restrict__ key_feats,
                                                    const float* __restrict__ q_w,
                                                    const float* __restrict__ q_b) {
    __shared__ float s_qk[QDIM];
    __shared__ float red[4];
    int c = blockIdx.x;
    int t = threadIdx.x;
    int warp = t >> 5, lane = t & 31;

    g_gvec[c][t] = 0.f;          // t covers all DIM=1024
    if (t == 0) g_Z[c] = 0.f;

    // qk[q] via warp-per-row dots (32 warps x 4 rounds = 128 rows)
    const float4* kr = (const float4*)(key_feats + (size_t)c * DIM);
    #pragma unroll
    for (int rr = 0; rr < 4; rr++) {
        int q = warp + rr * 32;
        const float4* qr = (const float4*)(q_w + (size_t)q * DIM);
        float a = 0.f;
        #pragma unroll
        for (int k = 0; k < 8; k++) {
            float4 x = qr[lane + k * 32], y = kr[lane + k * 32];
            a += x.x * y.x + x.y * y.y + x.z * y.z + x.w * y.w;
        }
        #pragma unroll
        for (int o = 16; o > 0; o >>= 1)
            a += __shfl_xor_sync(0xffffffffu, a, o);
        if (lane == 0) s_qk[q] = a + q_b[q];
    }
    __syncthreads();

    // w[t] = sum_q qk[q] * q_w[q][t]  (coalesced across t; MLP via unroll)
    float wacc = 0.f;
    #pragma unroll 16
    for (int q = 0; q < QDIM; q++)
        wacc += s_qk[q] * q_w[(size_t)q * DIM + t];
    g_w[c][t] = wacc;

    // b0 = qk . q_b (threads 0..127)
    if (t < QDIM) {
        float p = s_qk[t] * q_b[t];
        #pragma unroll
        for (int o = 16; o > 0; o >>= 1)
            p += __shfl_xor_sync(0xffffffffu, p, o);
        if (lane == 0) red[warp] = p;
    }
    __syncthreads();
    if (t == 0) g_b0[c] = red[0] + red[1] + red[2] + red[3];
}

// ---------------------------------------------------------------------------
// Kernel B (fused single pass over feats, register-resident rows):
// warp owns a row: loads 8 float4/lane, dot vs w (smem), s -> key (g_keys),
// e = exp(s), acc += e*row (registers). Block-combine + global atomics.
// grid = NC*64 (64 rows/block), block = 256 (8 warps x 8 rows each)
// ---------------------------------------------------------------------------
__global__ __launch_bounds__(256) void fused_pass_kernel(const float* __restrict__ feats) {
    __shared__ float sw[DIM];
    __shared__ float sacc[DIM];
    __shared__ float zsh;

    int bid = blockIdx.x;
    int c = bid >> 6;
    int base = (bid & 63) * 64;
    int t = threadIdx.x, warp = t >> 5, lane = t & 31;

    ((float4*)sw)[t] = ((const float4*)(g_w[c]))[t];
    ((float4*)sacc)[t] = make_float4(0.f, 0.f, 0.f, 0.f);
    if (t == 0) zsh = 0.f;
    float b0 = g_b0[c];
    __syncthreads();

    const float4* fb =
        (const float4*)(feats + ((size_t)c * NPER + base + (size_t)warp * 8) * DIM);

    float4 acc[8];
    #pragma unroll
    for (int k = 0; k < 8; k++) acc[k] = make_float4(0.f, 0.f, 0.f, 0.f);
    float zw = 0.f;

    for (int r = 0; r < 8; r++) {
        float4 f[8];
        #pragma unroll
        for (int k = 0; k < 8; k++)
            f[k] = fb[(size_t)r * 256 + lane + k * 32];

        float d = 0.f;
        #pragma unroll
        for (int k = 0; k < 8; k++) {
            float4 w4 = ((const float4*)sw)[lane + k * 32];
            d += f[k].x * w4.x + f[k].y * w4.y + f[k].z * w4.z + f[k].w * w4.w;
        }
        #pragma unroll
        for (int o = 16; o > 0; o >>= 1)
            d += __shfl_xor_sync(0xffffffffu, d, o);

        float s = (d + b0) * 0.08838834764831845f;  // 1/sqrt(128)
        float e = expf(s);                           // |s| small: safe
        zw += e;

        if (lane == 0) {
            int n = base + warp * 8 + r;
            unsigned u = __float_as_uint(s);
            u = (u & 0x80000000u) ? ~u : (u | 0x80000000u);  // ascending map
            unsigned dm = ~u;                                // descending map
            g_keys[c][n] = ((unsigned long long)dm << 32) | (unsigned)n;
        }

        #pragma unroll
        for (int k = 0; k < 8; k++) {
            acc[k].x += e * f[k].x; acc[k].y += e * f[k].y;
            acc[k].z += e * f[k].z; acc[k].w += e * f[k].w;
        }
    }

    // cross-warp combine (serialized rounds; cheap, once per block)
    for (int wi = 0; wi < 8; wi++) {
        if (warp == wi) {
            #pragma unroll
            for (int k = 0; k < 8; k++) {
                float4* p = &((float4*)sacc)[lane + k * 32];
                float4 v = *p;
                v.x += acc[k].x; v.y += acc[k].y;
                v.z += acc[k].z; v.w += acc[k].w;
                *p = v;
            }
            if (lane == 0) zsh += zw;
        }
        __syncthreads();
    }

    float4 v = ((float4*)sacc)[t];
    float* gp = g_gvec[c] + t * 4;
    atomicAdd(gp + 0, v.x);
    atomicAdd(gp + 1, v.y);
    atomicAdd(gp + 2, v.z);
    atomicAdd(gp + 3, v.w);
    if (t == 0) atomicAdd(&g_Z[c], zsh);
}

// ---------------------------------------------------------------------------
// Kernel C: exact top-128 via 8-level MSD radix select on 64-bit keys
// (all keys distinct: idx in low bits), then bitonic sort of 128 winners.
// grid = NC, block = 1024
// ---------------------------------------------------------------------------
__global__ __launch_bounds__(1024) void topk_kernel() {
    __shared__ unsigned hist[256];
    __shared__ unsigned long long s_prefix;
    __shared__ unsigned s_remaining;
    __shared__ unsigned long long winners[TOPK];
    __shared__ unsigned wcnt;

    int c = blockIdx.x;
    int t = threadIdx.x;

    unsigned long long key[4];
    #pragma unroll
    for (int i = 0; i < 4; i++) key[i] = g_keys[c][t + i * 1024];

    unsigned long long prefix = 0ull, mask = 0ull;
    unsigned remaining = TOPK;

    for (int level = 0; level < 8; level++) {
        int shift = 56 - 8 * level;
        if (t < 256) hist[t] = 0u;
        __syncthreads();

        #pragma unroll
        for (int i = 0; i < 4; i++) {
            if ((key[i] & mask) == prefix)
                atomicAdd(&hist[(unsigned)(key[i] >> shift) & 255u], 1u);
        }
        __syncthreads();

        unsigned own = (t < 256) ? hist[t] : 0u;
        // inclusive scan over 256 bins
        for (int off = 1; off < 256; off <<= 1) {
            unsigned v = 0u;
            if (t < 256 && t >= off) v = hist[t - off];
            __syncthreads();
            if (t < 256) hist[t] += v;
            __syncthreads();
        }
        if (t < 256) {
            unsigned incl = hist[t], excl = incl - own;
            if (own > 0 && excl < remaining && incl >= remaining) {
                s_prefix = prefix | ((unsigned long long)(unsigned)t << shift);
                s_remaining = remaining - excl;
            }
        }
        __syncthreads();
        prefix = s_prefix;
        remaining = s_remaining;
        mask |= (0xffull << shift);
        __syncthreads();
    }

    // prefix == exact 128th-smallest key; winners are keys <= prefix
    if (t == 0) wcnt = 0u;
    __syncthreads();
    #pragma unroll
    for (int i = 0; i < 4; i++) {
        if (key[i] <= prefix) {
            unsigned p = atomicAdd(&wcnt, 1u);
            winners[p] = key[i];
        }
    }
    __syncthreads();

    // bitonic sort 128 winners ascending (desc score, asc idx)
    for (unsigned k = 2; k <= TOPK; k <<= 1) {
        for (unsigned j = k >> 1; j > 0; j >>= 1) {
            if (t < TOPK) {
                unsigned i = (unsigned)t, ixj = i ^ j;
                if (ixj > i) {
                    unsigned long long a = winners[i], b = winners[ixj];
                    bool up = ((i & k) == 0);
                    if ((a > b) == up) { winners[i] = b; winners[ixj] = a; }
                }
            }
            __syncthreads();
        }
    }

    if (t < TOPK)
        g_topidx[c][t] = (int)(unsigned)(winners[t] & 0xffffffffu);
}

// ---------------------------------------------------------------------------
// Kernel D: gather selected rows: out[c*128+k] = feats[c][topidx[c][k]]
// grid = 1024, block = 256
// ---------------------------------------------------------------------------
__global__ void gather_kernel(const float* __restrict__ feats,
                              float* __restrict__ out) {
    int row = blockIdx.x;
    int c = row >> 7, k = row & 127;
    int src = g_topidx[c][k];
    const float4* s = (const float4*)(feats + ((size_t)c * NPER + src) * DIM);
    float4* dst = (float4*)(out + (size_t)row * DIM);
    dst[threadIdx.x] = s[threadIdx.x];
}

// ---------------------------------------------------------------------------
// Kernel E: fusion[c][o] = (gvec[c]/Z[c]) . v_w[o,:] + v_b[o]
// grid = NC*128 (8 outputs per block), block = 256 (8 warps)
// ---------------------------------------------------------------------------
__global__ void fusion_kernel(const float* __restrict__ v_w,
                              const float* __restrict__ v_b,
                              float* __restrict__ out) {
    __shared__ float sg[DIM];
    int bid = blockIdx.x;
    int c = bid >> 7;
    int o0 = (bid & 127) * 8;
    int t = threadIdx.x;

    float invZ = 1.f / g_Z[c];
    float4 gv = ((const float4*)(g_gvec[c]))[t];
    gv.x *= invZ; gv.y *= invZ; gv.z *= invZ; gv.w *= invZ;
    ((float4*)sg)[t] = gv;
    __syncthreads();

    int warp = t >> 5, lane = t & 31;
    int o = o0 + warp;
    const float4* vr = (const float4*)(v_w + (size_t)o * DIM);
    const float4* gr = (const float4*)sg;
    float acc = 0.f;
    #pragma unroll
    for (int i = 0; i < 8; i++) {
        int idx = lane + i * 32;
        float4 a = vr[idx], b = gr[idx];
        acc += a.x * b.x + a.y * b.y + a.z * b.z + a.w * b.w;
    }
    #pragma unroll
    for (int ofs = 16; ofs > 0; ofs >>= 1)
        acc += __shfl_xor_sync(0xffffffffu, acc, ofs);
    if (lane == 0)
        out[(size_t)1024 * 1024 + (size_t)c * DIM + o] = acc + v_b[o];
}

// ---------------------------------------------------------------------------
extern "C" void kernel_launch(void* const* d_in, const int* in_sizes, int n_in,
                              void* d_out, int out_size) {
    const float* feats     = (const float*)d_in[0];  // [8,4096,1024]
    const float* key_feats = (const float*)d_in[1];  // [8,1,1024]
    const float* q_w       = (const float*)d_in[2];  // [128,1024]
    const float* q_b       = (const float*)d_in[3];  // [128]
    const float* v_w       = (const float*)d_in[4];  // [1024,1024]
    const float* v_b       = (const float*)d_in[5];  // [1024]
    float* out = (float*)d_out;  // selected [1024,1024] then fus [8,1024]

    prep_kernel<<<NC, 1024>>>(key_feats, q_w, q_b);
    fused_pass_kernel<<<NC * 64, 256>>>(feats);
    topk_kernel<<<NC, 1024>>>();
    gather_kernel<<<NC * TOPK, 256>>>(feats, out);
    fusion_kernel<<<NC * 128, 256>>>(v_w, v_b, out);
}